// round 2
// baseline (speedup 1.0000x reference)
#include <cuda_runtime.h>
#include <cuda.h>
#include <cuda_fp16.h>
#include <cstdint>

// y[n,o] = sum_r sum_m A[r,n,m] * z[r,o,m],  z[r,o,m] = sum_i x[m,i] * W[r,o,i]
// Main GEMM: mma.sync fp16 (f32 accum), TMA-fed 3-stage k64 pipeline.
// Grid (16, 8): 256-row M-tile x single relation. Partials via atomicAdd.

#define NREL 8
#define NN   4096
#define NF   64

// z scratch, fp16, layout [r][o][m]
__device__ __half g_z[NREL * NF * NN];

// ---------------- PTX helpers ----------------
__device__ __forceinline__ uint32_t smem_u32(const void* p) {
    uint32_t a;
    asm("{ .reg .u64 t; cvta.to.shared.u64 t, %1; cvt.u32.u64 %0, t; }" : "=r"(a) : "l"(p));
    return a;
}

#define MBAR_INIT(addr, cnt) \
    asm volatile("mbarrier.init.shared.b64 [%0], %1;" :: "r"(addr), "r"(cnt) : "memory")

#define MBAR_EXPECT_TX(addr, bytes) \
    asm volatile("mbarrier.arrive.expect_tx.shared.b64 _, [%0], %1;" :: "r"(addr), "r"(bytes) : "memory")

#define MBAR_ARRIVE(addr) \
    asm volatile("mbarrier.arrive.shared.b64 _, [%0];" :: "r"(addr) : "memory")

#define MBAR_WAIT(mbar, parity) do {                                              \
    asm volatile("{\n\t.reg .pred P;\n\t"                                         \
        "WL%=:\n\t"                                                               \
        "mbarrier.try_wait.parity.acquire.cta.shared::cta.b64 P, [%0], %1, 0x989680;\n\t" \
        "@P bra.uni WD%=;\n\t"                                                    \
        "bra.uni WL%=;\n\t"                                                       \
        "WD%=:\n\t}"                                                              \
        :: "r"((uint32_t)(mbar)), "r"((uint32_t)(parity)) : "memory");            \
} while (0)

#define MBAR_WAIT_RELAXED(mbar, parity) do {                                      \
    asm volatile("{\n\t.reg .pred P;\n\t"                                         \
        "WL%=:\n\t"                                                               \
        "mbarrier.try_wait.parity.relaxed.cta.shared::cta.b64 P, [%0], %1, 0x989680;\n\t" \
        "@P bra.uni WD%=;\n\t"                                                    \
        "bra.uni WL%=;\n\t"                                                       \
        "WD%=:\n\t}"                                                              \
        :: "r"((uint32_t)(mbar)), "r"((uint32_t)(parity)) : "memory");            \
} while (0)

#define TMA_LD3(smem_addr, map, cx, cy, cz, mbar)                                 \
    asm volatile("cp.async.bulk.tensor.3d.shared::cta.global.tile.mbarrier::complete_tx::bytes " \
        "[%0], [%1, {%2, %3, %4}], [%5];"                                         \
        :: "r"((uint32_t)(smem_addr)), "l"(map), "r"((int)(cx)), "r"((int)(cy)),  \
           "r"((int)(cz)), "r"((uint32_t)(mbar)) : "memory")

__device__ __forceinline__ void mma16816(float* c, const uint32_t* a, const uint32_t* b) {
    asm volatile("mma.sync.aligned.m16n8k16.row.col.f32.f16.f16.f32 "
        "{%0,%1,%2,%3}, {%4,%5,%6,%7}, {%8,%9}, {%0,%1,%2,%3};"
        : "+f"(c[0]), "+f"(c[1]), "+f"(c[2]), "+f"(c[3])
        : "r"(a[0]), "r"(a[1]), "r"(a[2]), "r"(a[3]), "r"(b[0]), "r"(b[1]));
}

// load float2 from smem and pack to f16x2 (low half = first element)
__device__ __forceinline__ uint32_t lds_f2_to_h2(uint32_t addr) {
    float x, y;
    asm volatile("ld.shared.v2.f32 {%0,%1}, [%2];" : "=f"(x), "=f"(y) : "r"(addr));
    uint32_t d;
    asm volatile("cvt.rn.f16x2.f32 %0, %1, %2;" : "=r"(d) : "f"(y), "f"(x));
    return d;
}

__device__ __forceinline__ uint32_t lds_u32(uint32_t addr) {
    uint32_t d;
    asm volatile("ld.shared.u32 %0, [%1];" : "=r"(d) : "r"(addr));
    return d;
}

// ---------------- config ----------------
constexpr int NSTAGES      = 3;
constexpr int KSTAGE       = 64;                  // k elems per stage
constexpr int STAGE_A0     = 0;                   // 256 rows x 128B (k 0..31)
constexpr int STAGE_A1     = 32768;               // 256 rows x 128B (k 32..63)
constexpr int STAGE_B      = 65536;               // 64 rows x 128B (fp16 k 0..63)
constexpr int STAGE_BYTES  = 73728;
constexpr int SMEM_REQ     = 1024 + NSTAGES * STAGE_BYTES;  // 222208

// ---------------- kernels ----------------
__global__ void zero_out_kernel(float4* out) {
    out[blockIdx.x * 256 + threadIdx.x] = make_float4(0.f, 0.f, 0.f, 0.f);
}

// z[r,o,m] = sum_i x[m,i]*W[r,o,i], stored fp16 (rna)
__global__ __launch_bounds__(256) void compute_z_kernel(const float* __restrict__ x,
                                                        const float* __restrict__ w) {
    __shared__ float xs[128 * 64];
    const int m0 = blockIdx.x * 128;
    const int r  = blockIdx.y;
    const int tid = threadIdx.x;

    const float4* xg = (const float4*)(x + (size_t)m0 * 64);
    float4* xs4 = (float4*)xs;
    for (int i = tid; i < 128 * 16; i += 256) xs4[i] = xg[i];
    __syncthreads();

    const int o  = tid & 63;
    const int ms = tid >> 6;

    float wr[64];
    const float4* wg = (const float4*)(w + ((size_t)(r * 64 + o)) * 64);
#pragma unroll
    for (int i = 0; i < 16; i++) {
        float4 v = wg[i];
        wr[4 * i] = v.x; wr[4 * i + 1] = v.y; wr[4 * i + 2] = v.z; wr[4 * i + 3] = v.w;
    }

    for (int mi = ms; mi < 128; mi += 4) {
        const float4* xr = (const float4*)(xs + mi * 64);
        float acc = 0.f;
#pragma unroll
        for (int i = 0; i < 16; i++) {
            float4 v = xr[i];
            acc += v.x * wr[4 * i] + v.y * wr[4 * i + 1] + v.z * wr[4 * i + 2] + v.w * wr[4 * i + 3];
        }
        g_z[((size_t)(r * 64 + o)) * NN + (m0 + mi)] = __float2half_rn(acc);
    }
}

// Main GEMM. 160 threads: warps 0-3 consumers (64 rows each), warp 4 TMA producer.
__global__ __launch_bounds__(160, 1) void rgcn_main_kernel(
    const __grid_constant__ CUtensorMap tma_a,
    const __grid_constant__ CUtensorMap tma_b,
    float* __restrict__ out) {
    extern __shared__ char smem[];
    const uint32_t sb = smem_u32(smem);
    const int tid  = threadIdx.x;
    const int wid  = tid >> 5;
    const int lane = tid & 31;

    // barriers: full[s] = sb + 16s, empty[s] = sb + 16s + 8
    const uint32_t data0 = (sb + 48 + 1023) & ~1023u;

    if (tid == 0) {
        for (int s = 0; s < NSTAGES; s++) {
            MBAR_INIT(sb + 16 * s, 1);      // full (tx-based)
            MBAR_INIT(sb + 16 * s + 8, 4);  // empty (4 consumer warps)
        }
    }
    __syncthreads();

    const int NITER = NN / KSTAGE;  // 64

    if (wid == 4) {
        // ---- producer ----
        if (lane == 0) {
            const int mrow = blockIdx.x * 256;
            const int rel  = blockIdx.y;
            int s = 0, p = 1;
            for (int it = 0; it < NITER; it++) {
                MBAR_WAIT_RELAXED(sb + 16 * s + 8, p);
                MBAR_EXPECT_TX(sb + 16 * s, STAGE_BYTES);
                const uint32_t st = data0 + s * STAGE_BYTES;
                const int k0 = it * KSTAGE;
                TMA_LD3(st + STAGE_A0, &tma_a, k0,      mrow, rel, sb + 16 * s);
                TMA_LD3(st + STAGE_A1, &tma_a, k0 + 32, mrow, rel, sb + 16 * s);
                TMA_LD3(st + STAGE_B,  &tma_b, k0,      0,    rel, sb + 16 * s);
                if (++s == NSTAGES) { s = 0; p ^= 1; }
            }
        }
    } else {
        // ---- consumers ----
        const int w  = wid;
        const int lr = lane >> 2;
        const int cp = lane & 3;
        const uint32_t sw = (uint32_t)lr << 4;

        uint32_t a_off0[4], a_off2[4], b_off0[4], b_off1[4];
#pragma unroll
        for (int ks = 0; ks < 4; ks++) {
            const uint32_t tb = (ks >> 1) ? STAGE_A1 : STAGE_A0;
            a_off0[ks] = tb + ((((ks & 1) * 64) + cp * 8)      ^ sw);
            a_off2[ks] = tb + ((((ks & 1) * 64) + cp * 8 + 32) ^ sw);
            b_off0[ks] = STAGE_B + (((uint32_t)(ks * 32 + cp * 4))      ^ sw);
            b_off1[ks] = STAGE_B + (((uint32_t)(ks * 32 + cp * 4 + 16)) ^ sw);
        }
        uint32_t rowb[4], ob[8];
#pragma unroll
        for (int mt = 0; mt < 4; mt++) rowb[mt] = (uint32_t)(w * 64 + mt * 16 + lr) * 128;
#pragma unroll
        for (int nt = 0; nt < 8; nt++) ob[nt] = (uint32_t)(nt * 8 + lr) * 128;

        float acc[4][8][4];
#pragma unroll
        for (int mt = 0; mt < 4; mt++)
#pragma unroll
            for (int nt = 0; nt < 8; nt++)
#pragma unroll
                for (int i = 0; i < 4; i++) acc[mt][nt][i] = 0.f;

        int s = 0, p = 0;
        for (int it = 0; it < NITER; it++) {
            MBAR_WAIT(sb + 16 * s, p);
            const uint32_t st = data0 + s * STAGE_BYTES;
#pragma unroll
            for (int ks = 0; ks < 4; ks++) {
                uint32_t bf[8][2];
#pragma unroll
                for (int nt = 0; nt < 8; nt++) {
                    bf[nt][0] = lds_u32(st + ob[nt] + b_off0[ks]);
                    bf[nt][1] = lds_u32(st + ob[nt] + b_off1[ks]);
                }
#pragma unroll
                for (int mt = 0; mt < 4; mt++) {
                    const uint32_t rb = st + rowb[mt];
                    uint32_t af[4];
                    af[0] = lds_f2_to_h2(rb +        a_off0[ks]);
                    af[1] = lds_f2_to_h2(rb + 1024 + a_off0[ks]);
                    af[2] = lds_f2_to_h2(rb +        a_off2[ks]);
                    af[3] = lds_f2_to_h2(rb + 1024 + a_off2[ks]);
#pragma unroll
                    for (int nt = 0; nt < 8; nt++)
                        mma16816(acc[mt][nt], af, bf[nt]);
                }
            }
            if (lane == 0) MBAR_ARRIVE(sb + 16 * s + 8);
            if (++s == NSTAGES) { s = 0; p ^= 1; }
        }

        // epilogue: accumulate partial into out
        const int rbase = blockIdx.x * 256 + w * 64;
#pragma unroll
        for (int mt = 0; mt < 4; mt++) {
#pragma unroll
            for (int nt = 0; nt < 8; nt++) {
                const int row = rbase + mt * 16 + lr;
                const int col = nt * 8 + cp * 2;
                atomicAdd(out + (size_t)row * 64 + col,           acc[mt][nt][0]);
                atomicAdd(out + (size_t)row * 64 + col + 1,       acc[mt][nt][1]);
                atomicAdd(out + (size_t)(row + 8) * 64 + col,     acc[mt][nt][2]);
                atomicAdd(out + (size_t)(row + 8) * 64 + col + 1, acc[mt][nt][3]);
            }
        }
    }
}

// ---------------- host ----------------
typedef CUresult (*PFN_encodeTiled)(CUtensorMap*, CUtensorMapDataType, cuuint32_t, void*,
                                    const cuuint64_t*, const cuuint64_t*, const cuuint32_t*,
                                    const cuuint32_t*, CUtensorMapInterleave, CUtensorMapSwizzle,
                                    CUtensorMapL2promotion, CUtensorMapFloatOOBfill);

extern "C" void kernel_launch(void* const* d_in, const int* in_sizes, int n_in,
                              void* d_out, int out_size) {
    const float* adj = nullptr;
    const float* x = nullptr;
    const float* w = nullptr;
    for (int i = 0; i < n_in; i++) {
        if (in_sizes[i] == NREL * NN * NN)      adj = (const float*)d_in[i];
        else if (in_sizes[i] == NN * NF)        x   = (const float*)d_in[i];
        else if (in_sizes[i] == NREL * NF * NF) w   = (const float*)d_in[i];
    }
    float* out = (float*)d_out;

    void* zptr = nullptr;
    cudaGetSymbolAddress(&zptr, g_z);

    void* fnp = nullptr;
    cudaDriverEntryPointQueryResult qst;
    cudaGetDriverEntryPointByVersion("cuTensorMapEncodeTiled", &fnp, 12000,
                                     cudaEnableDefault, &qst);
    PFN_encodeTiled encode = (PFN_encodeTiled)fnp;

    CUtensorMap tma_a{}, tma_b{};
    {
        cuuint64_t dims[3]    = {NN, NN, NREL};
        cuuint64_t strides[2] = {(cuuint64_t)NN * 4, (cuuint64_t)NN * NN * 4};
        cuuint32_t box[3]     = {32, 256, 1};
        cuuint32_t es[3]      = {1, 1, 1};
        encode(&tma_a, CU_TENSOR_MAP_DATA_TYPE_FLOAT32, 3, (void*)adj, dims, strides, box, es,
               CU_TENSOR_MAP_INTERLEAVE_NONE, CU_TENSOR_MAP_SWIZZLE_128B,
               CU_TENSOR_MAP_L2_PROMOTION_L2_128B, CU_TENSOR_MAP_FLOAT_OOB_FILL_NONE);
    }
    {
        cuuint64_t dims[3]    = {NN, NF, NREL};
        cuuint64_t strides[2] = {(cuuint64_t)NN * 2, (cuuint64_t)NF * NN * 2};
        cuuint32_t box[3]     = {64, 64, 1};
        cuuint32_t es[3]      = {1, 1, 1};
        encode(&tma_b, CU_TENSOR_MAP_DATA_TYPE_FLOAT16, 3, zptr, dims, strides, box, es,
               CU_TENSOR_MAP_INTERLEAVE_NONE, CU_TENSOR_MAP_SWIZZLE_128B,
               CU_TENSOR_MAP_L2_PROMOTION_L2_128B, CU_TENSOR_MAP_FLOAT_OOB_FILL_NONE);
    }

    cudaFuncSetAttribute(rgcn_main_kernel, cudaFuncAttributeMaxDynamicSharedMemorySize, SMEM_REQ);

    zero_out_kernel<<<256, 256>>>((float4*)out);       // 262144 floats
    compute_z_kernel<<<dim3(32, 8), 256>>>(x, w);
    rgcn_main_kernel<<<dim3(16, 8), 160, SMEM_REQ>>>(tma_a, tma_b, out);
}

// round 3
// speedup vs baseline: 1.0621x; 1.0621x over previous
#include <cuda_runtime.h>
#include <cuda.h>
#include <cuda_fp16.h>
#include <cstdint>

// y[n,o] = sum_r sum_m A[r,n,m] * z[r,o,m],  z[r,o,m] = sum_i x[m,i] * W[r,o,i]
// Main GEMM: mma.sync fp16 (f32 accum), TMA-fed 3-stage k64 pipeline.
// Grid (16, 8): 256-row M-tile x single relation. 8 consumer warps (2/SMSP).

#define NREL 8
#define NN   4096
#define NF   64

// z scratch, fp16, layout [r][o][m]
__device__ __half g_z[NREL * NF * NN];

// ---------------- PTX helpers ----------------
__device__ __forceinline__ uint32_t smem_u32(const void* p) {
    uint32_t a;
    asm("{ .reg .u64 t; cvta.to.shared.u64 t, %1; cvt.u32.u64 %0, t; }" : "=r"(a) : "l"(p));
    return a;
}

#define MBAR_INIT(addr, cnt) \
    asm volatile("mbarrier.init.shared.b64 [%0], %1;" :: "r"(addr), "r"(cnt) : "memory")

#define MBAR_EXPECT_TX(addr, bytes) \
    asm volatile("mbarrier.arrive.expect_tx.shared.b64 _, [%0], %1;" :: "r"(addr), "r"(bytes) : "memory")

#define MBAR_ARRIVE(addr) \
    asm volatile("mbarrier.arrive.shared.b64 _, [%0];" :: "r"(addr) : "memory")

#define MBAR_WAIT(mbar, parity) do {                                              \
    asm volatile("{\n\t.reg .pred P;\n\t"                                         \
        "WL%=:\n\t"                                                               \
        "mbarrier.try_wait.parity.acquire.cta.shared::cta.b64 P, [%0], %1, 0x989680;\n\t" \
        "@P bra.uni WD%=;\n\t"                                                    \
        "bra.uni WL%=;\n\t"                                                       \
        "WD%=:\n\t}"                                                              \
        :: "r"((uint32_t)(mbar)), "r"((uint32_t)(parity)) : "memory");            \
} while (0)

#define MBAR_WAIT_RELAXED(mbar, parity) do {                                      \
    asm volatile("{\n\t.reg .pred P;\n\t"                                         \
        "WL%=:\n\t"                                                               \
        "mbarrier.try_wait.parity.relaxed.cta.shared::cta.b64 P, [%0], %1, 0x989680;\n\t" \
        "@P bra.uni WD%=;\n\t"                                                    \
        "bra.uni WL%=;\n\t"                                                       \
        "WD%=:\n\t}"                                                              \
        :: "r"((uint32_t)(mbar)), "r"((uint32_t)(parity)) : "memory");            \
} while (0)

#define TMA_LD3(smem_addr, map, cx, cy, cz, mbar)                                 \
    asm volatile("cp.async.bulk.tensor.3d.shared::cta.global.tile.mbarrier::complete_tx::bytes " \
        "[%0], [%1, {%2, %3, %4}], [%5];"                                         \
        :: "r"((uint32_t)(smem_addr)), "l"(map), "r"((int)(cx)), "r"((int)(cy)),  \
           "r"((int)(cz)), "r"((uint32_t)(mbar)) : "memory")

__device__ __forceinline__ void mma16816(float* c, const uint32_t* a, const uint32_t* b) {
    asm volatile("mma.sync.aligned.m16n8k16.row.col.f32.f16.f16.f32 "
        "{%0,%1,%2,%3}, {%4,%5,%6,%7}, {%8,%9}, {%0,%1,%2,%3};"
        : "+f"(c[0]), "+f"(c[1]), "+f"(c[2]), "+f"(c[3])
        : "r"(a[0]), "r"(a[1]), "r"(a[2]), "r"(a[3]), "r"(b[0]), "r"(b[1]));
}

// load float2 from smem and pack to f16x2 (low half = first element)
__device__ __forceinline__ uint32_t lds_f2_to_h2(uint32_t addr) {
    float x, y;
    asm volatile("ld.shared.v2.f32 {%0,%1}, [%2];" : "=f"(x), "=f"(y) : "r"(addr));
    uint32_t d;
    asm volatile("cvt.rn.f16x2.f32 %0, %1, %2;" : "=r"(d) : "f"(y), "f"(x));
    return d;
}

__device__ __forceinline__ uint32_t lds_u32(uint32_t addr) {
    uint32_t d;
    asm volatile("ld.shared.u32 %0, [%1];" : "=r"(d) : "r"(addr));
    return d;
}

// ---------------- config ----------------
constexpr int NSTAGES      = 3;
constexpr int KSTAGE       = 64;                  // k elems per stage
constexpr int STAGE_A0     = 0;                   // 256 rows x 128B (k 0..31)
constexpr int STAGE_A1     = 32768;               // 256 rows x 128B (k 32..63)
constexpr int STAGE_B      = 65536;               // 64 rows x 128B (fp16 k 0..63)
constexpr int STAGE_BYTES  = 73728;
constexpr int SMEM_REQ     = 1024 + NSTAGES * STAGE_BYTES;  // 222208

// ---------------- kernels ----------------

// Fused: zero d_out + z[r,o,m] = sum_i x[m,i]*W[r,o,i] (fp16 store).
// Grid (16, 8), 256 threads. Thread owns one m-row of x in registers;
// W[r] broadcast from smem; stores coalesced (lanes = consecutive m).
__global__ __launch_bounds__(256) void compute_z_kernel(const float* __restrict__ x,
                                                        const float* __restrict__ w,
                                                        float4* __restrict__ out4) {
    __shared__ float ws[64 * 64];
    const int tid = threadIdx.x;
    const int r   = blockIdx.y;
    const int m   = blockIdx.x * 256 + tid;

    // zero output: 128 blocks x 512 float4 = 65536 float4 = 262144 floats
    const int bid = blockIdx.y * gridDim.x + blockIdx.x;
    const float4 z4 = make_float4(0.f, 0.f, 0.f, 0.f);
    out4[bid * 512 + tid]       = z4;
    out4[bid * 512 + 256 + tid] = z4;

    // load W[r] (64x64) into smem
    const float4* wg = (const float4*)(w + (size_t)r * 4096);
    float4* ws4 = (float4*)ws;
#pragma unroll
    for (int i = tid; i < 1024; i += 256) ws4[i] = wg[i];
    __syncthreads();

    // x row in registers
    float4 xr[16];
    const float4* xg = (const float4*)(x + (size_t)m * 64);
#pragma unroll
    for (int i = 0; i < 16; i++) xr[i] = xg[i];

    __half* zp = g_z + (size_t)r * 64 * NN + m;
    for (int o = 0; o < 64; o++) {
        const float4* wrow = (const float4*)(ws + o * 64);
        float acc = 0.f;
#pragma unroll
        for (int i = 0; i < 16; i++) {
            float4 wv = wrow[i];
            acc += xr[i].x * wv.x + xr[i].y * wv.y + xr[i].z * wv.z + xr[i].w * wv.w;
        }
        zp[(size_t)o * NN] = __float2half_rn(acc);
    }
}

// Main GEMM. 288 threads: warps 0-7 consumers (32 rows each), warp 8 TMA producer.
__global__ __launch_bounds__(288, 1) void rgcn_main_kernel(
    const __grid_constant__ CUtensorMap tma_a,
    const __grid_constant__ CUtensorMap tma_b,
    float* __restrict__ out) {
    extern __shared__ char smem[];
    const uint32_t sb = smem_u32(smem);
    const int tid  = threadIdx.x;
    const int wid  = tid >> 5;
    const int lane = tid & 31;

    // barriers: full[s] = sb + 16s, empty[s] = sb + 16s + 8
    const uint32_t data0 = (sb + 48 + 1023) & ~1023u;

    if (tid == 0) {
        for (int s = 0; s < NSTAGES; s++) {
            MBAR_INIT(sb + 16 * s, 1);      // full (tx-based)
            MBAR_INIT(sb + 16 * s + 8, 8);  // empty (8 consumer warps)
        }
    }
    __syncthreads();

    const int NITER = NN / KSTAGE;  // 64

    if (wid == 8) {
        // ---- producer ----
        if (lane == 0) {
            const int mrow = blockIdx.x * 256;
            const int rel  = blockIdx.y;
            int s = 0, p = 1;
            for (int it = 0; it < NITER; it++) {
                MBAR_WAIT_RELAXED(sb + 16 * s + 8, p);
                MBAR_EXPECT_TX(sb + 16 * s, STAGE_BYTES);
                const uint32_t st = data0 + s * STAGE_BYTES;
                const int k0 = it * KSTAGE;
                TMA_LD3(st + STAGE_A0, &tma_a, k0,      mrow, rel, sb + 16 * s);
                TMA_LD3(st + STAGE_A1, &tma_a, k0 + 32, mrow, rel, sb + 16 * s);
                TMA_LD3(st + STAGE_B,  &tma_b, k0,      0,    rel, sb + 16 * s);
                if (++s == NSTAGES) { s = 0; p ^= 1; }
            }
        }
    } else {
        // ---- consumers: warp w owns rows [w*32, w*32+32) of the 256-row tile ----
        const int w  = wid;
        const int lr = lane >> 2;
        const int cp = lane & 3;
        const uint32_t sw = (uint32_t)lr << 4;

        uint32_t a_off0[4], a_off2[4], b_off0[4], b_off1[4];
#pragma unroll
        for (int ks = 0; ks < 4; ks++) {
            const uint32_t tb = (ks >> 1) ? STAGE_A1 : STAGE_A0;
            a_off0[ks] = tb + ((((ks & 1) * 64) + cp * 8)      ^ sw);
            a_off2[ks] = tb + ((((ks & 1) * 64) + cp * 8 + 32) ^ sw);
            b_off0[ks] = STAGE_B + (((uint32_t)(ks * 32 + cp * 4))      ^ sw);
            b_off1[ks] = STAGE_B + (((uint32_t)(ks * 32 + cp * 4 + 16)) ^ sw);
        }
        uint32_t rowb[2], ob[8];
#pragma unroll
        for (int mt = 0; mt < 2; mt++) rowb[mt] = (uint32_t)(w * 32 + mt * 16 + lr) * 128;
#pragma unroll
        for (int nt = 0; nt < 8; nt++) ob[nt] = (uint32_t)(nt * 8 + lr) * 128;

        float acc[2][8][4];
#pragma unroll
        for (int mt = 0; mt < 2; mt++)
#pragma unroll
            for (int nt = 0; nt < 8; nt++)
#pragma unroll
                for (int i = 0; i < 4; i++) acc[mt][nt][i] = 0.f;

        int s = 0, p = 0;
        for (int it = 0; it < NITER; it++) {
            MBAR_WAIT(sb + 16 * s, p);
            const uint32_t st = data0 + s * STAGE_BYTES;
#pragma unroll
            for (int ks = 0; ks < 4; ks++) {
                uint32_t bf[8][2];
#pragma unroll
                for (int nt = 0; nt < 8; nt++) {
                    bf[nt][0] = lds_u32(st + ob[nt] + b_off0[ks]);
                    bf[nt][1] = lds_u32(st + ob[nt] + b_off1[ks]);
                }
#pragma unroll
                for (int mt = 0; mt < 2; mt++) {
                    const uint32_t rb = st + rowb[mt];
                    uint32_t af[4];
                    af[0] = lds_f2_to_h2(rb +        a_off0[ks]);
                    af[1] = lds_f2_to_h2(rb + 1024 + a_off0[ks]);
                    af[2] = lds_f2_to_h2(rb +        a_off2[ks]);
                    af[3] = lds_f2_to_h2(rb + 1024 + a_off2[ks]);
#pragma unroll
                    for (int nt = 0; nt < 8; nt++)
                        mma16816(acc[mt][nt], af, bf[nt]);
                }
            }
            if (lane == 0) MBAR_ARRIVE(sb + 16 * s + 8);
            if (++s == NSTAGES) { s = 0; p ^= 1; }
        }

        // epilogue: accumulate partial into out
        const int rbase = blockIdx.x * 256 + w * 32;
#pragma unroll
        for (int mt = 0; mt < 2; mt++) {
#pragma unroll
            for (int nt = 0; nt < 8; nt++) {
                const int row = rbase + mt * 16 + lr;
                const int col = nt * 8 + cp * 2;
                atomicAdd(out + (size_t)row * 64 + col,           acc[mt][nt][0]);
                atomicAdd(out + (size_t)row * 64 + col + 1,       acc[mt][nt][1]);
                atomicAdd(out + (size_t)(row + 8) * 64 + col,     acc[mt][nt][2]);
                atomicAdd(out + (size_t)(row + 8) * 64 + col + 1, acc[mt][nt][3]);
            }
        }
    }
}

// ---------------- host ----------------
typedef CUresult (*PFN_encodeTiled)(CUtensorMap*, CUtensorMapDataType, cuuint32_t, void*,
                                    const cuuint64_t*, const cuuint64_t*, const cuuint32_t*,
                                    const cuuint32_t*, CUtensorMapInterleave, CUtensorMapSwizzle,
                                    CUtensorMapL2promotion, CUtensorMapFloatOOBfill);

extern "C" void kernel_launch(void* const* d_in, const int* in_sizes, int n_in,
                              void* d_out, int out_size) {
    const float* adj = nullptr;
    const float* x = nullptr;
    const float* w = nullptr;
    for (int i = 0; i < n_in; i++) {
        if (in_sizes[i] == NREL * NN * NN)      adj = (const float*)d_in[i];
        else if (in_sizes[i] == NN * NF)        x   = (const float*)d_in[i];
        else if (in_sizes[i] == NREL * NF * NF) w   = (const float*)d_in[i];
    }
    float* out = (float*)d_out;

    void* zptr = nullptr;
    cudaGetSymbolAddress(&zptr, g_z);

    void* fnp = nullptr;
    cudaDriverEntryPointQueryResult qst;
    cudaGetDriverEntryPointByVersion("cuTensorMapEncodeTiled", &fnp, 12000,
                                     cudaEnableDefault, &qst);
    PFN_encodeTiled encode = (PFN_encodeTiled)fnp;

    CUtensorMap tma_a{}, tma_b{};
    {
        cuuint64_t dims[3]    = {NN, NN, NREL};
        cuuint64_t strides[2] = {(cuuint64_t)NN * 4, (cuuint64_t)NN * NN * 4};
        cuuint32_t box[3]     = {32, 256, 1};
        cuuint32_t es[3]      = {1, 1, 1};
        encode(&tma_a, CU_TENSOR_MAP_DATA_TYPE_FLOAT32, 3, (void*)adj, dims, strides, box, es,
               CU_TENSOR_MAP_INTERLEAVE_NONE, CU_TENSOR_MAP_SWIZZLE_128B,
               CU_TENSOR_MAP_L2_PROMOTION_L2_128B, CU_TENSOR_MAP_FLOAT_OOB_FILL_NONE);
    }
    {
        cuuint64_t dims[3]    = {NN, NF, NREL};
        cuuint64_t strides[2] = {(cuuint64_t)NN * 2, (cuuint64_t)NF * NN * 2};
        cuuint32_t box[3]     = {64, 64, 1};
        cuuint32_t es[3]      = {1, 1, 1};
        encode(&tma_b, CU_TENSOR_MAP_DATA_TYPE_FLOAT16, 3, zptr, dims, strides, box, es,
               CU_TENSOR_MAP_INTERLEAVE_NONE, CU_TENSOR_MAP_SWIZZLE_128B,
               CU_TENSOR_MAP_L2_PROMOTION_L2_128B, CU_TENSOR_MAP_FLOAT_OOB_FILL_NONE);
    }

    cudaFuncSetAttribute(rgcn_main_kernel, cudaFuncAttributeMaxDynamicSharedMemorySize, SMEM_REQ);

    compute_z_kernel<<<dim3(16, 8), 256>>>(x, w, (float4*)out);
    rgcn_main_kernel<<<dim3(16, 8), 288, SMEM_REQ>>>(tma_a, tma_b, out);
}

// round 6
// speedup vs baseline: 1.1437x; 1.0768x over previous
#include <cuda_runtime.h>
#include <cuda.h>
#include <cuda_fp16.h>
#include <cstdint>

// y[n,o] = sum_r sum_m A[r,n,m] * z[r,o,m],  z[r,o,m] = sum_i x[m,i] * W[r,o,i]
// Main GEMM: mma.sync fp16 (f32 accum), TMA-fed 5-stage k32 pipeline, occ=2.
// Grid (32, 8): 128-row M-tile x single relation. Partials via atomicAdd.

#define NREL 8
#define NN   4096
#define NF   64

// z scratch, fp16, layout [r][o][m]
__device__ __half g_z[NREL * NF * NN];

// ---------------- PTX helpers ----------------
__device__ __forceinline__ uint32_t smem_u32(const void* p) {
    uint32_t a;
    asm("{ .reg .u64 t; cvta.to.shared.u64 t, %1; cvt.u32.u64 %0, t; }" : "=r"(a) : "l"(p));
    return a;
}

#define MBAR_INIT(addr, cnt) \
    asm volatile("mbarrier.init.shared.b64 [%0], %1;" :: "r"(addr), "r"(cnt) : "memory")

#define MBAR_EXPECT_TX(addr, bytes) \
    asm volatile("mbarrier.arrive.expect_tx.shared.b64 _, [%0], %1;" :: "r"(addr), "r"(bytes) : "memory")

#define MBAR_ARRIVE(addr) \
    asm volatile("mbarrier.arrive.shared.b64 _, [%0];" :: "r"(addr) : "memory")

#define MBAR_WAIT(mbar, parity) do {                                              \
    asm volatile("{\n\t.reg .pred P;\n\t"                                         \
        "WL%=:\n\t"                                                               \
        "mbarrier.try_wait.parity.acquire.cta.shared::cta.b64 P, [%0], %1, 0x989680;\n\t" \
        "@P bra.uni WD%=;\n\t"                                                    \
        "bra.uni WL%=;\n\t"                                                       \
        "WD%=:\n\t}"                                                              \
        :: "r"((uint32_t)(mbar)), "r"((uint32_t)(parity)) : "memory");            \
} while (0)

#define MBAR_WAIT_RELAXED(mbar, parity) do {                                      \
    asm volatile("{\n\t.reg .pred P;\n\t"                                         \
        "WL%=:\n\t"                                                               \
        "mbarrier.try_wait.parity.relaxed.cta.shared::cta.b64 P, [%0], %1, 0x989680;\n\t" \
        "@P bra.uni WD%=;\n\t"                                                    \
        "bra.uni WL%=;\n\t"                                                       \
        "WD%=:\n\t}"                                                              \
        :: "r"((uint32_t)(mbar)), "r"((uint32_t)(parity)) : "memory");            \
} while (0)

#define TMA_LD3(smem_addr, map, cx, cy, cz, mbar)                                 \
    asm volatile("cp.async.bulk.tensor.3d.shared::cta.global.tile.mbarrier::complete_tx::bytes " \
        "[%0], [%1, {%2, %3, %4}], [%5];"                                         \
        :: "r"((uint32_t)(smem_addr)), "l"(map), "r"((int)(cx)), "r"((int)(cy)),  \
           "r"((int)(cz)), "r"((uint32_t)(mbar)) : "memory")

__device__ __forceinline__ void mma16816(float* c, const uint32_t* a, const uint32_t* b) {
    asm volatile("mma.sync.aligned.m16n8k16.row.col.f32.f16.f16.f32 "
        "{%0,%1,%2,%3}, {%4,%5,%6,%7}, {%8,%9}, {%0,%1,%2,%3};"
        : "+f"(c[0]), "+f"(c[1]), "+f"(c[2]), "+f"(c[3])
        : "r"(a[0]), "r"(a[1]), "r"(a[2]), "r"(a[3]), "r"(b[0]), "r"(b[1]));
}

// load float2 from smem and pack to f16x2 (low half = first element)
__device__ __forceinline__ uint32_t lds_f2_to_h2(uint32_t addr) {
    float x, y;
    asm volatile("ld.shared.v2.f32 {%0,%1}, [%2];" : "=f"(x), "=f"(y) : "r"(addr));
    uint32_t d;
    asm volatile("cvt.rn.f16x2.f32 %0, %1, %2;" : "=r"(d) : "f"(y), "f"(x));
    return d;
}

__device__ __forceinline__ uint32_t lds_u32(uint32_t addr) {
    uint32_t d;
    asm volatile("ld.shared.u32 %0, [%1];" : "=r"(d) : "r"(addr));
    return d;
}

// ---------------- config ----------------
constexpr int NSTAGES      = 5;
constexpr int KSTAGE       = 32;                    // k elems per stage
constexpr int STAGE_A      = 0;                     // 128 rows x 128B fp32 (k32)
constexpr int STAGE_B      = 16384;                 // 64 rows x 64B fp16 (k32)
constexpr int STAGE_BYTES  = 20480;
constexpr int SMEM_REQ     = 1024 + NSTAGES * STAGE_BYTES;  // 103424

// ---------------- kernels ----------------

// Fused: zero d_out + z[r,o,m] = sum_i x[m,i]*W[r,o,i] (fp16 store).
// Grid (16, 8), 256 threads. 4-way split accumulators for ILP.
__global__ __launch_bounds__(256) void compute_z_kernel(const float* __restrict__ x,
                                                        const float* __restrict__ w,
                                                        float4* __restrict__ out4) {
    __shared__ float ws[64 * 64];
    const int tid = threadIdx.x;
    const int r   = blockIdx.y;
    const int m   = blockIdx.x * 256 + tid;

    // zero output: 128 blocks x 512 float4 = 65536 float4 = 262144 floats
    const int bid = blockIdx.y * gridDim.x + blockIdx.x;
    const float4 z4 = make_float4(0.f, 0.f, 0.f, 0.f);
    out4[bid * 512 + tid]       = z4;
    out4[bid * 512 + 256 + tid] = z4;

    // load W[r] (64x64) into smem
    const float4* wg = (const float4*)(w + (size_t)r * 4096);
    float4* ws4 = (float4*)ws;
#pragma unroll
    for (int i = tid; i < 1024; i += 256) ws4[i] = wg[i];
    __syncthreads();

    // x row in registers
    float4 xr[16];
    const float4* xg = (const float4*)(x + (size_t)m * 64);
#pragma unroll
    for (int i = 0; i < 16; i++) xr[i] = xg[i];

    __half* zp = g_z + (size_t)r * 64 * NN + m;
    for (int o = 0; o < 64; o++) {
        const float4* wrow = (const float4*)(ws + o * 64);
        float a0 = 0.f, a1 = 0.f, a2 = 0.f, a3 = 0.f;
#pragma unroll
        for (int i = 0; i < 16; i += 4) {
            float4 w0 = wrow[i], w1 = wrow[i + 1], w2 = wrow[i + 2], w3 = wrow[i + 3];
            a0 += xr[i].x * w0.x + xr[i].y * w0.y + xr[i].z * w0.z + xr[i].w * w0.w;
            a1 += xr[i+1].x * w1.x + xr[i+1].y * w1.y + xr[i+1].z * w1.z + xr[i+1].w * w1.w;
            a2 += xr[i+2].x * w2.x + xr[i+2].y * w2.y + xr[i+2].z * w2.z + xr[i+2].w * w2.w;
            a3 += xr[i+3].x * w3.x + xr[i+3].y * w3.y + xr[i+3].z * w3.z + xr[i+3].w * w3.w;
        }
        zp[(size_t)o * NN] = __float2half_rn((a0 + a1) + (a2 + a3));
    }
}

// Main GEMM. 160 threads: warps 0-3 consumers (32 rows each), warp 4 TMA producer.
// 2 CTAs per SM (grid 256 on 148 SMs).
__global__ __launch_bounds__(160, 2) void rgcn_main_kernel(
    const __grid_constant__ CUtensorMap tma_a,
    const __grid_constant__ CUtensorMap tma_b,
    float* __restrict__ out) {
    extern __shared__ char smem[];
    const uint32_t sb = smem_u32(smem);
    const int tid  = threadIdx.x;
    const int wid  = tid >> 5;
    const int lane = tid & 31;

    // barriers: full[s] = sb + 16s, empty[s] = sb + 16s + 8
    const uint32_t data0 = (sb + NSTAGES * 16 + 1023) & ~1023u;

    if (tid == 0) {
        for (int s = 0; s < NSTAGES; s++) {
            MBAR_INIT(sb + 16 * s, 1);      // full (tx-based)
            MBAR_INIT(sb + 16 * s + 8, 4);  // empty (4 consumer warps)
        }
    }
    __syncthreads();

    const int NITER = NN / KSTAGE;  // 128

    if (wid == 4) {
        // ---- producer ----
        if (lane == 0) {
            const int mrow = blockIdx.x * 128;
            const int rel  = blockIdx.y;
            int s = 0, p = 1;
            for (int it = 0; it < NITER; it++) {
                MBAR_WAIT_RELAXED(sb + 16 * s + 8, p);
                MBAR_EXPECT_TX(sb + 16 * s, STAGE_BYTES);
                const uint32_t st = data0 + s * STAGE_BYTES;
                const int k0 = it * KSTAGE;
                TMA_LD3(st + STAGE_A, &tma_a, k0, mrow, rel, sb + 16 * s);
                TMA_LD3(st + STAGE_B, &tma_b, k0, 0,    rel, sb + 16 * s);
                if (++s == NSTAGES) { s = 0; p ^= 1; }
            }
        }
    } else {
        // ---- consumers: warp w owns rows [w*32, w*32+32) of the 128-row tile ----
        const int w  = wid;
        const int lr = lane >> 2;
        const int cp = lane & 3;
        const uint32_t swa = (uint32_t)lr << 4;        // SW128 (A, 128B rows)
        const uint32_t swb = (uint32_t)(lr & 6) << 3;  // SW64  (B, 64B rows)

        // ks in {0,1}: k16 halves of the k32 stage
        uint32_t a_off0[2], a_off2[2], b_off0[2], b_off1[2];
#pragma unroll
        for (int ks = 0; ks < 2; ks++) {
            a_off0[ks] = ((uint32_t)(ks * 64 + cp * 8))      ^ swa;
            a_off2[ks] = ((uint32_t)(ks * 64 + cp * 8 + 32)) ^ swa;
            b_off0[ks] = ((uint32_t)(ks * 32 + cp * 4))      ^ swb;
            b_off1[ks] = ((uint32_t)(ks * 32 + cp * 4 + 16)) ^ swb;
        }
        uint32_t rowb[2], ob[8];
#pragma unroll
        for (int mt = 0; mt < 2; mt++) rowb[mt] = (uint32_t)(w * 32 + mt * 16 + lr) * 128;
#pragma unroll
        for (int nt = 0; nt < 8; nt++) ob[nt] = STAGE_B + (uint32_t)(nt * 8 + lr) * 64;

        float acc[2][8][4];
#pragma unroll
        for (int mt = 0; mt < 2; mt++)
#pragma unroll
            for (int nt = 0; nt < 8; nt++)
#pragma unroll
                for (int i = 0; i < 4; i++) acc[mt][nt][i] = 0.f;

        int s = 0, p = 0;
        for (int it = 0; it < NITER; it++) {
            MBAR_WAIT(sb + 16 * s, p);
            const uint32_t st = data0 + s * STAGE_BYTES;
#pragma unroll
            for (int ks = 0; ks < 2; ks++) {
                uint32_t bf[8][2];
#pragma unroll
                for (int nt = 0; nt < 8; nt++) {
                    bf[nt][0] = lds_u32(st + ob[nt] + b_off0[ks]);
                    bf[nt][1] = lds_u32(st + ob[nt] + b_off1[ks]);
                }
#pragma unroll
                for (int mt = 0; mt < 2; mt++) {
                    const uint32_t rb = st + rowb[mt];
                    uint32_t af[4];
                    af[0] = lds_f2_to_h2(rb +        a_off0[ks]);
                    af[1] = lds_f2_to_h2(rb + 1024 + a_off0[ks]);
                    af[2] = lds_f2_to_h2(rb +        a_off2[ks]);
                    af[3] = lds_f2_to_h2(rb + 1024 + a_off2[ks]);
#pragma unroll
                    for (int nt = 0; nt < 8; nt++)
                        mma16816(acc[mt][nt], af, bf[nt]);
                }
            }
            if (lane == 0) MBAR_ARRIVE(sb + 16 * s + 8);
            if (++s == NSTAGES) { s = 0; p ^= 1; }
        }

        // epilogue: accumulate partial into out
        const int rbase = blockIdx.x * 128 + w * 32;
#pragma unroll
        for (int mt = 0; mt < 2; mt++) {
#pragma unroll
            for (int nt = 0; nt < 8; nt++) {
                const int row = rbase + mt * 16 + lr;
                const int col = nt * 8 + cp * 2;
                atomicAdd(out + (size_t)row * 64 + col,           acc[mt][nt][0]);
                atomicAdd(out + (size_t)row * 64 + col + 1,       acc[mt][nt][1]);
                atomicAdd(out + (size_t)(row + 8) * 64 + col,     acc[mt][nt][2]);
                atomicAdd(out + (size_t)(row + 8) * 64 + col + 1, acc[mt][nt][3]);
            }
        }
    }
}

// ---------------- host ----------------
typedef CUresult (*PFN_encodeTiled)(CUtensorMap*, CUtensorMapDataType, cuuint32_t, void*,
                                    const cuuint64_t*, const cuuint64_t*, const cuuint32_t*,
                                    const cuuint32_t*, CUtensorMapInterleave, CUtensorMapSwizzle,
                                    CUtensorMapL2promotion, CUtensorMapFloatOOBfill);

extern "C" void kernel_launch(void* const* d_in, const int* in_sizes, int n_in,
                              void* d_out, int out_size) {
    const float* adj = nullptr;
    const float* x = nullptr;
    const float* w = nullptr;
    for (int i = 0; i < n_in; i++) {
        if (in_sizes[i] == NREL * NN * NN)      adj = (const float*)d_in[i];
        else if (in_sizes[i] == NN * NF)        x   = (const float*)d_in[i];
        else if (in_sizes[i] == NREL * NF * NF) w   = (const float*)d_in[i];
    }
    float* out = (float*)d_out;

    void* zptr = nullptr;
    cudaGetSymbolAddress(&zptr, g_z);

    void* fnp = nullptr;
    cudaDriverEntryPointQueryResult qst;
    cudaGetDriverEntryPointByVersion("cuTensorMapEncodeTiled", &fnp, 12000,
                                     cudaEnableDefault, &qst);
    PFN_encodeTiled encode = (PFN_encodeTiled)fnp;

    CUtensorMap tma_a{}, tma_b{};
    {
        cuuint64_t dims[3]    = {NN, NN, NREL};
        cuuint64_t strides[2] = {(cuuint64_t)NN * 4, (cuuint64_t)NN * NN * 4};
        cuuint32_t box[3]     = {32, 128, 1};
        cuuint32_t es[3]      = {1, 1, 1};
        encode(&tma_a, CU_TENSOR_MAP_DATA_TYPE_FLOAT32, 3, (void*)adj, dims, strides, box, es,
               CU_TENSOR_MAP_INTERLEAVE_NONE, CU_TENSOR_MAP_SWIZZLE_128B,
               CU_TENSOR_MAP_L2_PROMOTION_L2_128B, CU_TENSOR_MAP_FLOAT_OOB_FILL_NONE);
    }
    {
        cuuint64_t dims[3]    = {NN, NF, NREL};
        cuuint64_t strides[2] = {(cuuint64_t)NN * 2, (cuuint64_t)NF * NN * 2};
        cuuint32_t box[3]     = {32, 64, 1};
        cuuint32_t es[3]      = {1, 1, 1};
        encode(&tma_b, CU_TENSOR_MAP_DATA_TYPE_FLOAT16, 3, zptr, dims, strides, box, es,
               CU_TENSOR_MAP_INTERLEAVE_NONE, CU_TENSOR_MAP_SWIZZLE_64B,
               CU_TENSOR_MAP_L2_PROMOTION_L2_128B, CU_TENSOR_MAP_FLOAT_OOB_FILL_NONE);
    }

    cudaFuncSetAttribute(rgcn_main_kernel, cudaFuncAttributeMaxDynamicSharedMemorySize, SMEM_REQ);

    compute_z_kernel<<<dim3(16, 8), 256>>>(x, w, (float4*)out);
    rgcn_main_kernel<<<dim3(32, 8), 160, SMEM_REQ>>>(tma_a, tma_b, out);
}

// round 7
// speedup vs baseline: 1.3261x; 1.1595x over previous
#include <cuda_runtime.h>
#include <cuda.h>
#include <cuda_fp16.h>
#include <cstdint>

// y[n,o] = sum_r sum_m A[r,n,m] * z[r,o,m],  z[r,o,m] = sum_i x[m,i] * W[r,o,i]
// Main GEMM: mma.sync fp16 (f32 accum), TMA-fed 5-stage k32 pipeline, occ=2,
// A descriptor uses L2_PROMOTION_256B to fix DRAM row-activation efficiency.
// z computed with mma.sync fp16 as well (tensor pipe, not FFMA floor).

#define NREL 8
#define NN   4096
#define NF   64

// z scratch, fp16, layout [r][o][m]
__device__ __half g_z[NREL * NF * NN];

// ---------------- PTX helpers ----------------
__device__ __forceinline__ uint32_t smem_u32(const void* p) {
    uint32_t a;
    asm("{ .reg .u64 t; cvta.to.shared.u64 t, %1; cvt.u32.u64 %0, t; }" : "=r"(a) : "l"(p));
    return a;
}

#define MBAR_INIT(addr, cnt) \
    asm volatile("mbarrier.init.shared.b64 [%0], %1;" :: "r"(addr), "r"(cnt) : "memory")

#define MBAR_EXPECT_TX(addr, bytes) \
    asm volatile("mbarrier.arrive.expect_tx.shared.b64 _, [%0], %1;" :: "r"(addr), "r"(bytes) : "memory")

#define MBAR_ARRIVE(addr) \
    asm volatile("mbarrier.arrive.shared.b64 _, [%0];" :: "r"(addr) : "memory")

#define MBAR_WAIT(mbar, parity) do {                                              \
    asm volatile("{\n\t.reg .pred P;\n\t"                                         \
        "WL%=:\n\t"                                                               \
        "mbarrier.try_wait.parity.acquire.cta.shared::cta.b64 P, [%0], %1, 0x989680;\n\t" \
        "@P bra.uni WD%=;\n\t"                                                    \
        "bra.uni WL%=;\n\t"                                                       \
        "WD%=:\n\t}"                                                              \
        :: "r"((uint32_t)(mbar)), "r"((uint32_t)(parity)) : "memory");            \
} while (0)

#define MBAR_WAIT_RELAXED(mbar, parity) do {                                      \
    asm volatile("{\n\t.reg .pred P;\n\t"                                         \
        "WL%=:\n\t"                                                               \
        "mbarrier.try_wait.parity.relaxed.cta.shared::cta.b64 P, [%0], %1, 0x989680;\n\t" \
        "@P bra.uni WD%=;\n\t"                                                    \
        "bra.uni WL%=;\n\t"                                                       \
        "WD%=:\n\t}"                                                              \
        :: "r"((uint32_t)(mbar)), "r"((uint32_t)(parity)) : "memory");            \
} while (0)

#define TMA_LD3(smem_addr, map, cx, cy, cz, mbar)                                 \
    asm volatile("cp.async.bulk.tensor.3d.shared::cta.global.tile.mbarrier::complete_tx::bytes " \
        "[%0], [%1, {%2, %3, %4}], [%5];"                                         \
        :: "r"((uint32_t)(smem_addr)), "l"(map), "r"((int)(cx)), "r"((int)(cy)),  \
           "r"((int)(cz)), "r"((uint32_t)(mbar)) : "memory")

__device__ __forceinline__ void mma16816(float* c, const uint32_t* a, const uint32_t* b) {
    asm volatile("mma.sync.aligned.m16n8k16.row.col.f32.f16.f16.f32 "
        "{%0,%1,%2,%3}, {%4,%5,%6,%7}, {%8,%9}, {%0,%1,%2,%3};"
        : "+f"(c[0]), "+f"(c[1]), "+f"(c[2]), "+f"(c[3])
        : "r"(a[0]), "r"(a[1]), "r"(a[2]), "r"(a[3]), "r"(b[0]), "r"(b[1]));
}

// load float2 from smem and pack to f16x2 (low half = first element)
__device__ __forceinline__ uint32_t lds_f2_to_h2(uint32_t addr) {
    float x, y;
    asm volatile("ld.shared.v2.f32 {%0,%1}, [%2];" : "=f"(x), "=f"(y) : "r"(addr));
    uint32_t d;
    asm volatile("cvt.rn.f16x2.f32 %0, %1, %2;" : "=r"(d) : "f"(y), "f"(x));
    return d;
}

__device__ __forceinline__ uint32_t lds_u32(uint32_t addr) {
    uint32_t d;
    asm volatile("ld.shared.u32 %0, [%1];" : "=r"(d) : "r"(addr));
    return d;
}

// ---------------- config ----------------
constexpr int NSTAGES      = 5;
constexpr int KSTAGE       = 32;                    // k elems per stage
constexpr int STAGE_A      = 0;                     // 128 rows x 128B fp32 (k32)
constexpr int STAGE_B      = 16384;                 // 64 rows x 64B fp16 (k32)
constexpr int STAGE_BYTES  = 20480;
constexpr int SMEM_REQ     = 1024 + NSTAGES * STAGE_BYTES;  // 103424

// ---------------- kernels ----------------

// Fused: zero d_out + z[r,:,:] = W[r] @ x^T via mma.sync fp16.
// Grid (32, 8), 128 threads. Per block: D(64 o x 128 m), K=64.
// smem pitch 72 halves (144B) -> conflict-free fragment loads.
__global__ __launch_bounds__(128) void compute_z_kernel(const float* __restrict__ x,
                                                        const float* __restrict__ w,
                                                        float4* __restrict__ out4) {
    __shared__ __half wsm[64 * 72];
    __shared__ __half xsm[128 * 72];
    const int tid = threadIdx.x;
    const int r   = blockIdx.y;
    const int m0  = blockIdx.x * 128;

    // zero output: 256 blocks x 256 float4 = 65536 float4 = 262144 floats
    const int bid = blockIdx.y * 32 + blockIdx.x;
    const float4 z4 = make_float4(0.f, 0.f, 0.f, 0.f);
    out4[bid * 256 + tid]       = z4;
    out4[bid * 256 + 128 + tid] = z4;

    // W[r] (64x64 fp32) -> wsm fp16
    const float4* wg = (const float4*)(w + (size_t)r * 4096);
#pragma unroll
    for (int i = tid; i < 1024; i += 128) {
        float4 v = wg[i];
        const int row = i >> 4, col = (i & 15) * 4;
        __half2* d = (__half2*)(wsm + row * 72 + col);
        d[0] = __floats2half2_rn(v.x, v.y);
        d[1] = __floats2half2_rn(v.z, v.w);
    }
    // x[m0:m0+128] (128x64 fp32) -> xsm fp16
    const float4* xg = (const float4*)(x + (size_t)m0 * 64);
#pragma unroll
    for (int i = tid; i < 2048; i += 128) {
        float4 v = xg[i];
        const int row = i >> 4, col = (i & 15) * 4;
        __half2* d = (__half2*)(xsm + row * 72 + col);
        d[0] = __floats2half2_rn(v.x, v.y);
        d[1] = __floats2half2_rn(v.z, v.w);
    }
    __syncthreads();

    const int wid = tid >> 5, lane = tid & 31;
    const int gr = lane >> 2, cp = lane & 3;

    float acc[4][4][4];
#pragma unroll
    for (int ot = 0; ot < 4; ot++)
#pragma unroll
        for (int nt = 0; nt < 4; nt++)
#pragma unroll
            for (int i = 0; i < 4; i++) acc[ot][nt][i] = 0.f;

#pragma unroll
    for (int ks = 0; ks < 4; ks++) {
        const int kb = ks * 16 + cp * 2;  // halves
        uint32_t bf[4][2];
#pragma unroll
        for (int nt = 0; nt < 4; nt++) {
            const __half* bp = xsm + (wid * 32 + nt * 8 + gr) * 72 + kb;
            bf[nt][0] = *(const uint32_t*)bp;
            bf[nt][1] = *(const uint32_t*)(bp + 8);
        }
#pragma unroll
        for (int ot = 0; ot < 4; ot++) {
            const __half* ap = wsm + (ot * 16 + gr) * 72 + kb;
            uint32_t af[4];
            af[0] = *(const uint32_t*)ap;
            af[1] = *(const uint32_t*)(ap + 8 * 72);
            af[2] = *(const uint32_t*)(ap + 8);
            af[3] = *(const uint32_t*)(ap + 8 * 72 + 8);
#pragma unroll
            for (int nt = 0; nt < 4; nt++)
                mma16816(acc[ot][nt], af, bf[nt]);
        }
    }

    // store z fp16: D[o][m], c0/c1 -> (o, m..m+1), c2/c3 -> (o+8, ..)
#pragma unroll
    for (int ot = 0; ot < 4; ot++) {
#pragma unroll
        for (int nt = 0; nt < 4; nt++) {
            const int o = ot * 16 + gr;
            const int m = m0 + wid * 32 + nt * 8 + cp * 2;
            __half2* p0 = (__half2*)(g_z + ((size_t)(r * 64 + o)) * NN + m);
            __half2* p1 = (__half2*)(g_z + ((size_t)(r * 64 + o + 8)) * NN + m);
            *p0 = __floats2half2_rn(acc[ot][nt][0], acc[ot][nt][1]);
            *p1 = __floats2half2_rn(acc[ot][nt][2], acc[ot][nt][3]);
        }
    }
}

// Main GEMM. 160 threads: warps 0-3 consumers (32 rows each), warp 4 TMA producer.
// 2 CTAs per SM (grid 256 on 148 SMs).
__global__ __launch_bounds__(160, 2) void rgcn_main_kernel(
    const __grid_constant__ CUtensorMap tma_a,
    const __grid_constant__ CUtensorMap tma_b,
    float* __restrict__ out) {
    extern __shared__ char smem[];
    const uint32_t sb = smem_u32(smem);
    const int tid  = threadIdx.x;
    const int wid  = tid >> 5;
    const int lane = tid & 31;

    // barriers: full[s] = sb + 16s, empty[s] = sb + 16s + 8
    const uint32_t data0 = (sb + NSTAGES * 16 + 1023) & ~1023u;

    if (tid == 0) {
        for (int s = 0; s < NSTAGES; s++) {
            MBAR_INIT(sb + 16 * s, 1);      // full (tx-based)
            MBAR_INIT(sb + 16 * s + 8, 4);  // empty (4 consumer warps)
        }
    }
    __syncthreads();

    const int NITER = NN / KSTAGE;  // 128

    if (wid == 4) {
        // ---- producer ----
        if (lane == 0) {
            const int mrow = blockIdx.x * 128;
            const int rel  = blockIdx.y;
            int s = 0, p = 1;
            for (int it = 0; it < NITER; it++) {
                MBAR_WAIT_RELAXED(sb + 16 * s + 8, p);
                MBAR_EXPECT_TX(sb + 16 * s, STAGE_BYTES);
                const uint32_t st = data0 + s * STAGE_BYTES;
                const int k0 = it * KSTAGE;
                TMA_LD3(st + STAGE_A, &tma_a, k0, mrow, rel, sb + 16 * s);
                TMA_LD3(st + STAGE_B, &tma_b, k0, 0,    rel, sb + 16 * s);
                if (++s == NSTAGES) { s = 0; p ^= 1; }
            }
        }
    } else {
        // ---- consumers: warp w owns rows [w*32, w*32+32) of the 128-row tile ----
        const int w  = wid;
        const int lr = lane >> 2;
        const int cp = lane & 3;
        const uint32_t swa = (uint32_t)lr << 4;        // SW128 (A, 128B rows)
        const uint32_t swb = (uint32_t)(lr & 6) << 3;  // SW64  (B, 64B rows)

        // ks in {0,1}: k16 halves of the k32 stage
        uint32_t a_off0[2], a_off2[2], b_off0[2], b_off1[2];
#pragma unroll
        for (int ks = 0; ks < 2; ks++) {
            a_off0[ks] = ((uint32_t)(ks * 64 + cp * 8))      ^ swa;
            a_off2[ks] = ((uint32_t)(ks * 64 + cp * 8 + 32)) ^ swa;
            b_off0[ks] = ((uint32_t)(ks * 32 + cp * 4))      ^ swb;
            b_off1[ks] = ((uint32_t)(ks * 32 + cp * 4 + 16)) ^ swb;
        }
        uint32_t rowb[2], ob[8];
#pragma unroll
        for (int mt = 0; mt < 2; mt++) rowb[mt] = (uint32_t)(w * 32 + mt * 16 + lr) * 128;
#pragma unroll
        for (int nt = 0; nt < 8; nt++) ob[nt] = STAGE_B + (uint32_t)(nt * 8 + lr) * 64;

        float acc[2][8][4];
#pragma unroll
        for (int mt = 0; mt < 2; mt++)
#pragma unroll
            for (int nt = 0; nt < 8; nt++)
#pragma unroll
                for (int i = 0; i < 4; i++) acc[mt][nt][i] = 0.f;

        int s = 0, p = 0;
        for (int it = 0; it < NITER; it++) {
            MBAR_WAIT(sb + 16 * s, p);
            const uint32_t st = data0 + s * STAGE_BYTES;
#pragma unroll
            for (int ks = 0; ks < 2; ks++) {
                uint32_t bf[8][2];
#pragma unroll
                for (int nt = 0; nt < 8; nt++) {
                    bf[nt][0] = lds_u32(st + ob[nt] + b_off0[ks]);
                    bf[nt][1] = lds_u32(st + ob[nt] + b_off1[ks]);
                }
#pragma unroll
                for (int mt = 0; mt < 2; mt++) {
                    const uint32_t rb = st + rowb[mt];
                    uint32_t af[4];
                    af[0] = lds_f2_to_h2(rb +        a_off0[ks]);
                    af[1] = lds_f2_to_h2(rb + 1024 + a_off0[ks]);
                    af[2] = lds_f2_to_h2(rb +        a_off2[ks]);
                    af[3] = lds_f2_to_h2(rb + 1024 + a_off2[ks]);
#pragma unroll
                    for (int nt = 0; nt < 8; nt++)
                        mma16816(acc[mt][nt], af, bf[nt]);
                }
            }
            if (lane == 0) MBAR_ARRIVE(sb + 16 * s + 8);
            if (++s == NSTAGES) { s = 0; p ^= 1; }
        }

        // epilogue: accumulate partial into out
        const int rbase = blockIdx.x * 128 + w * 32;
#pragma unroll
        for (int mt = 0; mt < 2; mt++) {
#pragma unroll
            for (int nt = 0; nt < 8; nt++) {
                const int row = rbase + mt * 16 + lr;
                const int col = nt * 8 + cp * 2;
                atomicAdd(out + (size_t)row * 64 + col,           acc[mt][nt][0]);
                atomicAdd(out + (size_t)row * 64 + col + 1,       acc[mt][nt][1]);
                atomicAdd(out + (size_t)(row + 8) * 64 + col,     acc[mt][nt][2]);
                atomicAdd(out + (size_t)(row + 8) * 64 + col + 1, acc[mt][nt][3]);
            }
        }
    }
}

// ---------------- host ----------------
typedef CUresult (*PFN_encodeTiled)(CUtensorMap*, CUtensorMapDataType, cuuint32_t, void*,
                                    const cuuint64_t*, const cuuint64_t*, const cuuint32_t*,
                                    const cuuint32_t*, CUtensorMapInterleave, CUtensorMapSwizzle,
                                    CUtensorMapL2promotion, CUtensorMapFloatOOBfill);

extern "C" void kernel_launch(void* const* d_in, const int* in_sizes, int n_in,
                              void* d_out, int out_size) {
    const float* adj = nullptr;
    const float* x = nullptr;
    const float* w = nullptr;
    for (int i = 0; i < n_in; i++) {
        if (in_sizes[i] == NREL * NN * NN)      adj = (const float*)d_in[i];
        else if (in_sizes[i] == NN * NF)        x   = (const float*)d_in[i];
        else if (in_sizes[i] == NREL * NF * NF) w   = (const float*)d_in[i];
    }
    float* out = (float*)d_out;

    void* zptr = nullptr;
    cudaGetSymbolAddress(&zptr, g_z);

    void* fnp = nullptr;
    cudaDriverEntryPointQueryResult qst;
    cudaGetDriverEntryPointByVersion("cuTensorMapEncodeTiled", &fnp, 12000,
                                     cudaEnableDefault, &qst);
    PFN_encodeTiled encode = (PFN_encodeTiled)fnp;

    CUtensorMap tma_a{}, tma_b{};
    {
        cuuint64_t dims[3]    = {NN, NN, NREL};
        cuuint64_t strides[2] = {(cuuint64_t)NN * 4, (cuuint64_t)NN * NN * 4};
        cuuint32_t box[3]     = {32, 128, 1};
        cuuint32_t es[3]      = {1, 1, 1};
        encode(&tma_a, CU_TENSOR_MAP_DATA_TYPE_FLOAT32, 3, (void*)adj, dims, strides, box, es,
               CU_TENSOR_MAP_INTERLEAVE_NONE, CU_TENSOR_MAP_SWIZZLE_128B,
               CU_TENSOR_MAP_L2_PROMOTION_L2_256B, CU_TENSOR_MAP_FLOAT_OOB_FILL_NONE);
    }
    {
        cuuint64_t dims[3]    = {NN, NF, NREL};
        cuuint64_t strides[2] = {(cuuint64_t)NN * 2, (cuuint64_t)NF * NN * 2};
        cuuint32_t box[3]     = {32, 64, 1};
        cuuint32_t es[3]      = {1, 1, 1};
        encode(&tma_b, CU_TENSOR_MAP_DATA_TYPE_FLOAT16, 3, zptr, dims, strides, box, es,
               CU_TENSOR_MAP_INTERLEAVE_NONE, CU_TENSOR_MAP_SWIZZLE_64B,
               CU_TENSOR_MAP_L2_PROMOTION_L2_128B, CU_TENSOR_MAP_FLOAT_OOB_FILL_NONE);
    }

    cudaFuncSetAttribute(rgcn_main_kernel, cudaFuncAttributeMaxDynamicSharedMemorySize, SMEM_REQ);

    compute_z_kernel<<<dim3(32, 8), 128>>>(x, w, (float4*)out);
    rgcn_main_kernel<<<dim3(32, 8), 160, SMEM_REQ>>>(tma_a, tma_b, out);
}